// round 17
// baseline (speedup 1.0000x reference)
#include <cuda_runtime.h>
#include <cuda_fp16.h>
#include <cstdint>

#define B_   16
#define CI_  64
#define CO_  64
#define H_   128
#define W_   128
#define HO_  126
#define WO_  126
#define TAPS 9

// ---- device scratch (static; no allocation APIs) ----
// Single-pass fp16 (validated: rel_err 2.23e-4 << 1e-3).
__device__ __half g_xh[(size_t)B_ * H_ * W_ * CI_];
__device__ __half g_w[(size_t)B_ * TAPS * CO_ * CI_];

// ---- smem layout: p-tile 64, kTile 2; ALL taps resident ----
#define A_WROWS       66
#define A_ROW_BYTES   (A_WROWS * 128)          // 8448
#define SB_OFF        (4 * A_ROW_BYTES)        // 33792
#define B_TAP_BYTES   8192
#define SMEM_BYTES    (SB_OFF + TAPS * B_TAP_BYTES)   // 107520 -> 2 CTAs/SM
#define A_CHUNKS      (SB_OFF / 16)            // 2112

// ---- baseline-target PTX helpers ----
__device__ __forceinline__ uint32_t smem_u32(const void* p) {
    uint32_t a;
    asm("{ .reg .u64 t; cvta.to.shared.u64 t, %1; cvt.u32.u64 %0, t; }" : "=r"(a) : "l"(p));
    return a;
}
#define CPA16(dst, src) \
    asm volatile("cp.async.cg.shared.global [%0], [%1], 16;" :: "r"(dst), "l"(src))
#define CPA_COMMIT() asm volatile("cp.async.commit_group;" ::: "memory")
#define CPA_WAIT0()  asm volatile("cp.async.wait_group 0;" ::: "memory")

__device__ __forceinline__ void ldsm4(uint32_t addr, uint32_t r[4]) {
    asm volatile("ldmatrix.sync.aligned.m8n8.x4.shared.b16 {%0,%1,%2,%3}, [%4];"
        : "=r"(r[0]), "=r"(r[1]), "=r"(r[2]), "=r"(r[3]) : "r"(addr));
}
__device__ __forceinline__ void mma16816(float d[4], const uint32_t a[4],
                                         uint32_t b0, uint32_t b1) {
    asm volatile("mma.sync.aligned.m16n8k16.row.col.f32.f16.f16.f32 "
        "{%0,%1,%2,%3},{%4,%5,%6,%7},{%8,%9},{%0,%1,%2,%3};"
        : "+f"(d[0]), "+f"(d[1]), "+f"(d[2]), "+f"(d[3])
        : "r"(a[0]), "r"(a[1]), "r"(a[2]), "r"(a[3]), "r"(b0), "r"(b1));
}

// ---- prepass 1: x (B,CI,H,W) f32 -> fp16 [b*H+h][w][ci] ----
__global__ void __launch_bounds__(256) prepass_x(const float* __restrict__ x) {
    __shared__ float tile[64 * 129];
    const int t = threadIdx.x;
    const int h = blockIdx.x & 127, b = blockIdx.x >> 7;
    const float* xb = x + ((size_t)b * CI_ * H_ + h) * W_;

    #pragma unroll
    for (int j = 0; j < 8; j++) {
        int idx = j * 256 + t;
        int ci = idx >> 5, w4 = (idx & 31) << 2;
        const float4 v = *(const float4*)(xb + (size_t)ci * (H_ * W_) + w4);
        float* dst = tile + ci * 129 + w4;
        dst[0] = v.x; dst[1] = v.y; dst[2] = v.z; dst[3] = v.w;
    }
    __syncthreads();

    const int ci0 = (t & 7) * 8;
    #pragma unroll
    for (int i = 0; i < 4; i++) {
        int w = i * 32 + (t >> 3);
        __half h8[8];
        #pragma unroll
        for (int c = 0; c < 8; c++)
            h8[c] = __float2half(tile[(ci0 + c) * 129 + w]);
        size_t o = ((size_t)(b * H_ + h) * W_ + w) * CI_ + ci0;
        *(uint4*)(g_xh + o) = *(uint4*)h8;
    }
}

// ---- prepass 2: weight (B,CO,CI,3,3) f32 -> fp16 [b*9+t][co][ci] ----
__global__ void prepass_w(const float* __restrict__ wgt) {
    int idx = blockIdx.x * 256 + threadIdx.x;
    int ci = idx & 63, co = (idx >> 6) & 63, b = idx >> 12;
    const float* wp = wgt + (size_t)idx * TAPS;
    #pragma unroll
    for (int t = 0; t < TAPS; t++) {
        size_t o = ((size_t)(b * TAPS + t) * CO_ + co) * CI_ + ci;
        g_w[o] = __float2half(wp[t]);
    }
}

// ---- main: per (b, 2x oh, w-tile); kk-split warps, 64-co warp tile ----
__global__ void __launch_bounds__(256, 2)
conv_hmma(const float* __restrict__ bias, float* __restrict__ out) {
    extern __shared__ char sm[];
    const int tid  = threadIdx.x;
    const int lane = tid & 31, wid = tid >> 5;
    const int wt    = blockIdx.x & 1;
    const int rest  = blockIdx.x >> 1;
    const int b     = rest / (HO_ / 2);
    const int oh    = (rest - b * (HO_ / 2)) * 2;
    const int wbase = wt * 62;               // tiles: p 0..63 and p 62..125

    const int kkh   = wid & 1;                // 2-way kk (ci) split
    const int pbase = ((wid >> 1) & 1) * 32;  // 2 warps along p (64)
    const int ohl   = wid >> 2;               // 2 warps along oh

    const uint32_t sA = smem_u32(sm);
    const uint32_t sB = sA + SB_OFF;

    // ---- single prologue: A tile + ALL 9 B taps ----
    #pragma unroll
    for (int k = 0; k < 9; k++) {
        int i = tid + k * 256;
        if (i < A_CHUNKS) {
            int row = i / 528, rem2 = i - row * 528;
            int w = rem2 >> 3, c = rem2 & 7;
            uint32_t dst = sA + row * A_ROW_BYTES +
                           w * 128 + ((c ^ (w & 7)) << 4);
            const char* src = (const char*)
                (g_xh + (((size_t)(b * H_ + oh + row)) * W_ + wbase + w) * CI_ + c * 8);
            CPA16(dst, src);
        }
    }
    {
        const __half* gw = g_w + (size_t)b * TAPS * CO_ * CI_;
        #pragma unroll
        for (int k = 0; k < 18; k++) {
            int i = tid + k * 256;                 // tap*512 + co*8 + c
            int t = i >> 9, rem = i & 511;
            int co = rem >> 3, c = rem & 7;
            uint32_t dst = sB + t * B_TAP_BYTES +
                           co * 128 + (((c ^ (co & 7)) << 4));
            CPA16(dst, (const char*)(gw + ((size_t)t * CO_ + co) * CI_ + c * 8));
        }
    }
    CPA_COMMIT();
    CPA_WAIT0();
    __syncthreads();

    // lane constants
    const int dw = lane & 15, hi = lane >> 4;
    const int bco = (lane & 7) + ((lane >> 3) & 1) * 8;   // 0..15 row in 16-co block
    const int b7 = bco & 7;                                // same for all 4 blocks
    const int aw = pbase + dw;

    float acc[2][8][4];    // [m 2x16p][n 8x8co][4]
    #pragma unroll
    for (int m = 0; m < 2; m++)
        #pragma unroll
        for (int n = 0; n < 8; n++)
            #pragma unroll
            for (int e = 0; e < 4; e++) acc[m][n][e] = 0.f;

    // ---- barrier-free mainloop: 9 taps x 2 kk x (6 ldsm + 16 mma) ----
    #pragma unroll
    for (int t = 0; t < TAPS; t++) {
        const int kh = t / 3, kw = t % 3;
        const int w0 = aw + kw, w1 = w0 + 16;        // <= 65
        const int w07 = w0 & 7, w17 = w1 & 7;
        const uint32_t arow = sA + (kh + ohl) * A_ROW_BYTES;
        const uint32_t a0b = arow + w0 * 128, a1b = arow + w1 * 128;
        const uint32_t bb = sB + t * B_TAP_BYTES;

        #pragma unroll
        for (int kq = 0; kq < 2; kq++) {
            const int kc = (kkh * 2 + kq) * 2 + hi;   // kk = kkh*2+kq
            uint32_t bf[4][4];
            #pragma unroll
            for (int cb = 0; cb < 4; cb++)
                ldsm4(bb + (cb * 16 + bco) * 128 + ((kc ^ b7) << 4), bf[cb]);

            uint32_t ah0[4], ah1[4];
            ldsm4(a0b + ((kc ^ w07) << 4), ah0);
            ldsm4(a1b + ((kc ^ w17) << 4), ah1);

            #pragma unroll
            for (int n = 0; n < 8; n++) {
                const uint32_t* Bf = bf[n >> 1];
                const int s = n & 1;
                mma16816(acc[0][n], ah0, Bf[s], Bf[s + 2]);
                mma16816(acc[1][n], ah1, Bf[s], Bf[s + 2]);
            }
        }
    }

    // ---- epilogue: kk-pair reduction through smem, then coalesced out ----
    __syncthreads();   // ldsm reads done before smem reuse
    float* smf = (float*)sm;                 // [ohl 2][co 64][p 64] f32
    const int rowq = lane >> 2, colp = 2 * (lane & 3);
    float* sw = smf + ohl * 4096;

    if (kkh == 0) {
        #pragma unroll
        for (int m = 0; m < 2; m++)
            #pragma unroll
            for (int n = 0; n < 8; n++) {
                int p0 = pbase + m * 16 + rowq;
                int c0 = n * 8 + colp;
                sw[c0 * 64 + p0]           = acc[m][n][0];
                sw[(c0 + 1) * 64 + p0]     = acc[m][n][1];
                sw[c0 * 64 + p0 + 8]       = acc[m][n][2];
                sw[(c0 + 1) * 64 + p0 + 8] = acc[m][n][3];
            }
    }
    __syncthreads();
    if (kkh == 1) {
        #pragma unroll
        for (int m = 0; m < 2; m++)
            #pragma unroll
            for (int n = 0; n < 8; n++) {
                int p0 = pbase + m * 16 + rowq;
                int c0 = n * 8 + colp;
                sw[c0 * 64 + p0]           += acc[m][n][0];
                sw[(c0 + 1) * 64 + p0]     += acc[m][n][1];
                sw[c0 * 64 + p0 + 8]       += acc[m][n][2];
                sw[(c0 + 1) * 64 + p0 + 8] += acc[m][n][3];
            }
    }
    __syncthreads();

    const int co = tid >> 2, q = tid & 3;
    const float bv = bias[b * CO_ + co];
    #pragma unroll
    for (int o = 0; o < 2; o++) {
        float* op = out + ((size_t)(b * CO_ + co) * HO_ + oh + o) * WO_ + wbase;
        const float* sp = smf + o * 4096 + co * 64;
        #pragma unroll
        for (int i = 0; i < 16; i++) {
            int p = q * 16 + i;            // wbase+p <= 125: all valid
            op[p] = sp[p] + bv;
        }
    }
}

extern "C" void kernel_launch(void* const* d_in, const int* in_sizes, int n_in,
                              void* d_out, int out_size) {
    (void)in_sizes; (void)n_in; (void)out_size;
    const float* x    = (const float*)d_in[0];
    const float* wgt  = (const float*)d_in[1];
    const float* bias = (const float*)d_in[2];
    float* out        = (float*)d_out;

    static bool attr_set = false;
    if (!attr_set) {
        cudaFuncSetAttribute(conv_hmma, cudaFuncAttributeMaxDynamicSharedMemorySize,
                             SMEM_BYTES);
        attr_set = true;
    }

    prepass_x<<<B_ * H_, 256>>>(x);
    prepass_w<<<256, 256>>>(wgt);
    conv_hmma<<<2 * B_ * (HO_ / 2), 256, SMEM_BYTES>>>(bias, out);
}